// round 13
// baseline (speedup 1.0000x reference)
#include <cuda_runtime.h>
#include <cuda_bf16.h>

#define NN 50000
#define EEDGE 500000
#define GG 64
#define HH 2
#define FF 128          // H*D
#define CC 5
#define SLOPE 0.2f
#define SX 132          // padded bf16 row stride
#define GB1 6250        // warp-per-node blocks in fused1_k (50000/8)
#define HB1 1954        // hist blocks ((E+255)/256)

// ---------------- scratch (device globals) ------------------------------------
// Invariant across graph replays: g_deg, g_cursor are zero on entry to each
// replay (zero-initialized at load; re-zeroed inside the replay after last use).
__device__ float g_h[NN * FF];
__device__ float g_x[NN * FF];
__device__ float g_as[NN * HH];
__device__ float g_ad[NN * HH];
__device__ float g_pool[GG * FF];
__device__ float g_cnt[GG];
__device__ int   g_deg[NN];
__device__ int   g_cursor[NN];
__device__ int   g_rowptr[NN + 1];
__device__ int   g_csrc[EEDGE];

// ---------------- launch #1: fused layer-1 GEMM + alpha, plus hist -------------
__global__ void fused1_k(const float* __restrict__ x, const float* __restrict__ W,
                         const float* __restrict__ asrc, const float* __restrict__ adst,
                         const int* __restrict__ dstv, int* __restrict__ deg,
                         float* __restrict__ h, float* __restrict__ as_,
                         float* __restrict__ ad_) {
    if (blockIdx.x < GB1) {
        // ---- GEMM [N,4]x[4,128] + alpha, warp per node ----
        __shared__ float Ws[4 * FF];
        int tid = threadIdx.x;
        for (int i = tid; i < 4 * FF; i += 256) Ws[i] = W[i];   // FIXED: full 512 loaded
        __syncthreads();
        int n = blockIdx.x * 8 + (tid >> 5);
        int lane = tid & 31;
        const float* xr = x + n * 4;
        float x0 = xr[0], x1 = xr[1], x2 = xr[2], x3 = xr[3];
        float v0 = x0 * Ws[lane]       + x1 * Ws[128 + lane]       + x2 * Ws[256 + lane]       + x3 * Ws[384 + lane];
        float v1 = x0 * Ws[lane + 32]  + x1 * Ws[128 + lane + 32]  + x2 * Ws[256 + lane + 32]  + x3 * Ws[384 + lane + 32];
        float v2 = x0 * Ws[lane + 64]  + x1 * Ws[128 + lane + 64]  + x2 * Ws[256 + lane + 64]  + x3 * Ws[384 + lane + 64];
        float v3 = x0 * Ws[lane + 96]  + x1 * Ws[128 + lane + 96]  + x2 * Ws[256 + lane + 96]  + x3 * Ws[384 + lane + 96];
        float* hr = h + (size_t)n * FF;
        hr[lane] = v0; hr[lane + 32] = v1; hr[lane + 64] = v2; hr[lane + 96] = v3;
        float s0 = v0 * asrc[lane] + v1 * asrc[lane + 32];
        float d0 = v0 * adst[lane] + v1 * adst[lane + 32];
        float s1 = v2 * asrc[64 + lane] + v3 * asrc[96 + lane];
        float d1 = v2 * adst[64 + lane] + v3 * adst[96 + lane];
#pragma unroll
        for (int o = 16; o; o >>= 1) {
            s0 += __shfl_xor_sync(0xffffffffu, s0, o);
            d0 += __shfl_xor_sync(0xffffffffu, d0, o);
            s1 += __shfl_xor_sync(0xffffffffu, s1, o);
            d1 += __shfl_xor_sync(0xffffffffu, d1, o);
        }
        if (lane == 0) {
            as_[n * 2] = s0; as_[n * 2 + 1] = s1;
            ad_[n * 2] = d0; ad_[n * 2 + 1] = d1;
        }
    } else {
        // ---- hist: deg histogram of dst ----
        int e = (blockIdx.x - GB1) * 256 + threadIdx.x;
        if (e < EEDGE) atomicAdd(&deg[dstv[e]], 1);
    }
}

// ---------------- launch #2: scan (+ zero deg for next replay, zero pool) -----
__global__ void scan_k(int* __restrict__ deg, int* __restrict__ rowptr,
                       float* __restrict__ pooled, float* __restrict__ cnt) {
    __shared__ int part[1024];
    const int CH = (NN + 1023) / 1024;
    int t = threadIdx.x;
    for (int i = t; i < GG * FF; i += 1024) pooled[i] = 0.f;
    if (t < GG) cnt[t] = 0.f;

    int base = t * CH;
    int s = 0;
    for (int i = 0; i < CH; i++) {
        int idx = base + i;
        if (idx < NN) s += deg[idx];
    }
    part[t] = s;
    __syncthreads();
    for (int off = 1; off < 1024; off <<= 1) {
        int v = (t >= off) ? part[t - off] : 0;
        __syncthreads();
        part[t] += v;
        __syncthreads();
    }
    int run = (t == 0) ? 0 : part[t - 1];
    for (int i = 0; i < CH; i++) {
        int idx = base + i;
        if (idx <= NN) {
            rowptr[idx] = run;
            if (idx < NN) { run += deg[idx]; deg[idx] = 0; }  // restore invariant
        }
    }
}

// ---------------- launch #3: scatter -------------------------------------------
__global__ void scatter_k(const int* __restrict__ srcv, const int* __restrict__ dstv,
                          const int* __restrict__ rowptr, int* __restrict__ cursor,
                          int* __restrict__ csrc) {
    int e = blockIdx.x * blockDim.x + threadIdx.x;
    if (e >= EEDGE) return;
    int d = dstv[e];
    int pos = rowptr[d] + atomicAdd(&cursor[d], 1);
    csrc[pos] = srcv[e];
}

// ---------------- tensor-core GEMM (layers 2-4), alpha fused -------------------
__device__ __forceinline__ void mma_bf16(float* d, const unsigned* a, const unsigned* b) {
    asm volatile(
        "mma.sync.aligned.m16n8k16.row.col.f32.bf16.bf16.f32 "
        "{%0,%1,%2,%3}, {%4,%5,%6,%7}, {%8,%9}, {%0,%1,%2,%3};"
        : "+f"(d[0]), "+f"(d[1]), "+f"(d[2]), "+f"(d[3])
        : "r"(a[0]), "r"(a[1]), "r"(a[2]), "r"(a[3]), "r"(b[0]), "r"(b[1]));
}

__global__ void __launch_bounds__(256, 1)
gemm_tc_k(const float* __restrict__ X, const float* __restrict__ W,
          const float* __restrict__ asrc, const float* __restrict__ adst,
          float* __restrict__ h, float* __restrict__ as_, float* __restrict__ ad_) {
    extern __shared__ __nv_bfloat16 sm[];
    __nv_bfloat16* Xhi = sm;
    __nv_bfloat16* Xlo = sm + 128 * SX;
    __nv_bfloat16* Whi = sm + 2 * 128 * SX;
    __nv_bfloat16* Wlo = sm + 3 * 128 * SX;

    int tid = threadIdx.x;
    int row0 = blockIdx.x * 128;

    for (int i = tid; i < FF * FF; i += 256) {
        int k = i >> 7, n = i & 127;
        float w = W[i];
        __nv_bfloat16 hi = __float2bfloat16_rn(w);
        __nv_bfloat16 lo = __float2bfloat16_rn(w - __bfloat162float(hi));
        Whi[n * SX + k] = hi;
        Wlo[n * SX + k] = lo;
    }
    for (int i = tid; i < 128 * FF; i += 256) {
        int r = i >> 7, c = i & 127;
        int gr = row0 + r;
        float v = (gr < NN) ? X[(size_t)gr * FF + c] : 0.f;
        __nv_bfloat16 hi = __float2bfloat16_rn(v);
        __nv_bfloat16 lo = __float2bfloat16_rn(v - __bfloat162float(hi));
        Xhi[r * SX + c] = hi;
        Xlo[r * SX + c] = lo;
    }
    __syncthreads();

    int w = tid >> 5;
    int lane = tid & 31;
    int grp = lane >> 2, qd = lane & 3;
    int mr = (w & 3) * 32;
    int nc = (w >> 2) * 64;
    int head = nc >> 6;

    float acc[2][8][4];
#pragma unroll
    for (int mt = 0; mt < 2; mt++)
#pragma unroll
        for (int nt = 0; nt < 8; nt++)
#pragma unroll
            for (int q = 0; q < 4; q++) acc[mt][nt][q] = 0.f;

#pragma unroll 2
    for (int ks = 0; ks < 8; ks++) {
        int k0 = ks * 16;
        unsigned Ah[2][4], Al[2][4];
#pragma unroll
        for (int mt = 0; mt < 2; mt++) {
            int r = mr + mt * 16 + grp;
            int o = r * SX + k0 + qd * 2;
            Ah[mt][0] = *reinterpret_cast<const unsigned*>(&Xhi[o]);
            Ah[mt][1] = *reinterpret_cast<const unsigned*>(&Xhi[o + 8 * SX]);
            Ah[mt][2] = *reinterpret_cast<const unsigned*>(&Xhi[o + 8]);
            Ah[mt][3] = *reinterpret_cast<const unsigned*>(&Xhi[o + 8 * SX + 8]);
            Al[mt][0] = *reinterpret_cast<const unsigned*>(&Xlo[o]);
            Al[mt][1] = *reinterpret_cast<const unsigned*>(&Xlo[o + 8 * SX]);
            Al[mt][2] = *reinterpret_cast<const unsigned*>(&Xlo[o + 8]);
            Al[mt][3] = *reinterpret_cast<const unsigned*>(&Xlo[o + 8 * SX + 8]);
        }
        unsigned Bh[8][2], Bl[8][2];
#pragma unroll
        for (int nt = 0; nt < 8; nt++) {
            int cidx = nc + nt * 8 + grp;
            int o = cidx * SX + k0 + qd * 2;
            Bh[nt][0] = *reinterpret_cast<const unsigned*>(&Whi[o]);
            Bh[nt][1] = *reinterpret_cast<const unsigned*>(&Whi[o + 8]);
            Bl[nt][0] = *reinterpret_cast<const unsigned*>(&Wlo[o]);
            Bl[nt][1] = *reinterpret_cast<const unsigned*>(&Wlo[o + 8]);
        }
#pragma unroll
        for (int mt = 0; mt < 2; mt++)
#pragma unroll
            for (int nt = 0; nt < 8; nt++) {
                mma_bf16(acc[mt][nt], Ah[mt], Bh[nt]);
                mma_bf16(acc[mt][nt], Ah[mt], Bl[nt]);
                mma_bf16(acc[mt][nt], Al[mt], Bh[nt]);
            }
    }

    float av[8][2], dv[8][2];
#pragma unroll
    for (int nt = 0; nt < 8; nt++)
#pragma unroll
        for (int c = 0; c < 2; c++) {
            int col = head * 64 + nt * 8 + qd * 2 + c;
            av[nt][c] = asrc[col];
            dv[nt][c] = adst[col];
        }

#pragma unroll
    for (int mt = 0; mt < 2; mt++) {
        int r0 = row0 + mr + mt * 16 + grp;
        float sa = 0.f, sd = 0.f, sa2 = 0.f, sd2 = 0.f;
#pragma unroll
        for (int nt = 0; nt < 8; nt++) {
            int col = nc + nt * 8 + qd * 2;
            if (r0 < NN)
                *reinterpret_cast<float2*>(&h[(size_t)r0 * FF + col]) =
                    make_float2(acc[mt][nt][0], acc[mt][nt][1]);
            if (r0 + 8 < NN)
                *reinterpret_cast<float2*>(&h[(size_t)(r0 + 8) * FF + col]) =
                    make_float2(acc[mt][nt][2], acc[mt][nt][3]);
#pragma unroll
            for (int c = 0; c < 2; c++) {
                sa  += acc[mt][nt][c]     * av[nt][c];
                sd  += acc[mt][nt][c]     * dv[nt][c];
                sa2 += acc[mt][nt][2 + c] * av[nt][c];
                sd2 += acc[mt][nt][2 + c] * dv[nt][c];
            }
        }
#pragma unroll
        for (int o = 1; o <= 2; o <<= 1) {
            sa  += __shfl_xor_sync(0xffffffffu, sa,  o);
            sd  += __shfl_xor_sync(0xffffffffu, sd,  o);
            sa2 += __shfl_xor_sync(0xffffffffu, sa2, o);
            sd2 += __shfl_xor_sync(0xffffffffu, sd2, o);
        }
        if (qd == 0) {
            if (r0 < NN)     { as_[2 * r0 + head] = sa;        ad_[2 * r0 + head] = sd; }
            if (r0 + 8 < NN) { as_[2 * (r0 + 8) + head] = sa2; ad_[2 * (r0 + 8) + head] = sd2; }
        }
    }
}

// ---------------- fused aggregation --------------------------------------------
// Warp per node. Fast path (deg<=32): softmax in registers, then (idx,weight)
// staged in smem; gather in unpredicated groups of 8 (MLP=8) + remainder.
__global__ void agg_k(const int* __restrict__ rowptr, const int* __restrict__ csrc,
                      const float* __restrict__ as_, const float* __restrict__ ad_,
                      const float* __restrict__ h, const float* __restrict__ b,
                      float* __restrict__ xo, int* __restrict__ cz) {
    __shared__ int   sidx[8][32];
    __shared__ float swt0[8][32];
    __shared__ float swt1[8][32];
    int n = (blockIdx.x * blockDim.x + threadIdx.x) >> 5;
    int w = (threadIdx.x >> 5);
    int lane = threadIdx.x & 31;
    if (n >= NN) return;
    if (cz && lane == 0) cz[n] = 0;   // restore cursor invariant (layer 0 only)
    int beg = rowptr[n], end = rowptr[n + 1];
    int deg = end - beg;
    float ad0 = ad_[2 * n], ad1 = ad_[2 * n + 1];

    float4 acc = make_float4(0.f, 0.f, 0.f, 0.f);

    if (deg <= 32) {
        int sreg = 0;
        float e0 = -1e30f, e1 = -1e30f;
        if (lane < deg) {
            sreg = csrc[beg + lane];
            float2 sv = reinterpret_cast<const float2*>(as_)[sreg];
            e0 = sv.x + ad0; e0 = e0 > 0.f ? e0 : SLOPE * e0;
            e1 = sv.y + ad1; e1 = e1 > 0.f ? e1 : SLOPE * e1;
        }
        float m0 = e0, m1 = e1;
#pragma unroll
        for (int o = 16; o; o >>= 1) {
            m0 = fmaxf(m0, __shfl_xor_sync(0xffffffffu, m0, o));
            m1 = fmaxf(m1, __shfl_xor_sync(0xffffffffu, m1, o));
        }
        float p0 = (lane < deg) ? __expf(e0 - m0) : 0.f;
        float p1 = (lane < deg) ? __expf(e1 - m1) : 0.f;
        float s0 = p0, s1 = p1;
#pragma unroll
        for (int o = 16; o; o >>= 1) {
            s0 += __shfl_xor_sync(0xffffffffu, s0, o);
            s1 += __shfl_xor_sync(0xffffffffu, s1, o);
        }
        sidx[w][lane] = sreg;
        swt0[w][lane] = p0 / (s0 + 1e-16f);
        swt1[w][lane] = p1 / (s1 + 1e-16f);
        __syncwarp();

        const int*   si = sidx[w];
        const float* wp = (lane < 16) ? swt0[w] : swt1[w];

        int j = 0;
        for (; j + 8 <= deg; j += 8) {
            float4 v[8]; float wg[8];
#pragma unroll
            for (int u = 0; u < 8; u++) {
                int idx = si[j + u];
                wg[u] = wp[j + u];
                v[u] = reinterpret_cast<const float4*>(h + (size_t)idx * FF)[lane];
            }
#pragma unroll
            for (int u = 0; u < 8; u++) {
                acc.x += v[u].x * wg[u]; acc.y += v[u].y * wg[u];
                acc.z += v[u].z * wg[u]; acc.w += v[u].w * wg[u];
            }
        }
#pragma unroll
        for (int u = 0; u < 7; u++) {
            int jj = j + u;
            if (jj < deg) {
                int idx = si[jj];
                float wg = wp[jj];
                float4 v = reinterpret_cast<const float4*>(h + (size_t)idx * FF)[lane];
                acc.x += v.x * wg; acc.y += v.y * wg;
                acc.z += v.z * wg; acc.w += v.w * wg;
            }
        }
    } else {
        // fallback (rare): online softmax + sequential gather
        float m0 = -1e30f, s0 = 0.f, m1 = -1e30f, s1 = 0.f;
        for (int i = beg + lane; i < end; i += 32) {
            int s = csrc[i];
            float e0 = as_[2 * s] + ad0;     e0 = e0 > 0.f ? e0 : SLOPE * e0;
            float e1 = as_[2 * s + 1] + ad1; e1 = e1 > 0.f ? e1 : SLOPE * e1;
            float nm0 = fmaxf(m0, e0);
            s0 = s0 * __expf(m0 - nm0) + __expf(e0 - nm0); m0 = nm0;
            float nm1 = fmaxf(m1, e1);
            s1 = s1 * __expf(m1 - nm1) + __expf(e1 - nm1); m1 = nm1;
        }
#pragma unroll
        for (int o = 16; o; o >>= 1) {
            float om = __shfl_xor_sync(0xffffffffu, m0, o);
            float os = __shfl_xor_sync(0xffffffffu, s0, o);
            float nm = fmaxf(m0, om);
            s0 = s0 * __expf(m0 - nm) + os * __expf(om - nm); m0 = nm;
            om = __shfl_xor_sync(0xffffffffu, m1, o);
            os = __shfl_xor_sync(0xffffffffu, s1, o);
            nm = fmaxf(m1, om);
            s1 = s1 * __expf(m1 - nm) + os * __expf(om - nm); m1 = nm;
        }
        float inv0 = 1.f / (s0 + 1e-16f);
        float inv1 = 1.f / (s1 + 1e-16f);
        for (int i = beg; i < end; i++) {
            int s = csrc[i];
            float e0 = as_[2 * s] + ad0;     e0 = e0 > 0.f ? e0 : SLOPE * e0;
            float e1 = as_[2 * s + 1] + ad1; e1 = e1 > 0.f ? e1 : SLOPE * e1;
            float p = (lane < 16) ? __expf(e0 - m0) * inv0 : __expf(e1 - m1) * inv1;
            float4 v = reinterpret_cast<const float4*>(h + (size_t)s * FF)[lane];
            acc.x += v.x * p; acc.y += v.y * p; acc.z += v.z * p; acc.w += v.w * p;
        }
    }

    float4 bv = reinterpret_cast<const float4*>(b)[lane];
    float4 r;
    r.x = fmaxf(acc.x + bv.x, 0.f);
    r.y = fmaxf(acc.y + bv.y, 0.f);
    r.z = fmaxf(acc.z + bv.z, 0.f);
    r.w = fmaxf(acc.w + bv.w, 0.f);
    reinterpret_cast<float4*>(xo + (size_t)n * FF)[lane] = r;
}

// ---------------- pooling + classifier -----------------------------------------
#define PB 128
__global__ void pool_k(const int* __restrict__ batch, const float* __restrict__ x,
                       float* __restrict__ pooled, float* __restrict__ cnt) {
    int c = threadIdx.x;
    int n0 = blockIdx.x * PB;
    int nend = min(n0 + PB, NN);
    if (n0 >= NN) return;
    int curg = batch[n0];
    float run = 0.f;
    for (int n = n0; n < nend; n++) {
        int g = batch[n];
        if (g != curg) {
            atomicAdd(&pooled[curg * FF + c], run);
            run = 0.f; curg = g;
        }
        run += x[(size_t)n * FF + c];
    }
    atomicAdd(&pooled[curg * FF + c], run);
    if (c == 0) {
        int cg = batch[n0]; float cr = 0.f;
        for (int n = n0; n < nend; n++) {
            int g = batch[n];
            if (g != cg) { atomicAdd(&cnt[cg], cr); cr = 0.f; cg = g; }
            cr += 1.f;
        }
        atomicAdd(&cnt[cg], cr);
    }
}

__global__ void final_k(const float* __restrict__ pooled, const float* __restrict__ cnt,
                        const float* __restrict__ lw, const float* __restrict__ lb,
                        float* __restrict__ out) {
    int t = threadIdx.x;
    if (t >= GG * CC) return;
    int g = t / CC, c = t % CC;
    float inv = 1.f / fmaxf(cnt[g], 1.f);
    float acc = lb[c];
    for (int k = 0; k < FF; k++)
        acc += pooled[g * FF + k] * inv * lw[k * CC + c];
    out[t] = 1.f / (1.f + expf(-acc));
}

// ---------------- launch --------------------------------------------------------
extern "C" void kernel_launch(void* const* d_in, const int* in_sizes, int n_in,
                              void* d_out, int out_size) {
    const float* x     = (const float*)d_in[0];
    const int*   ei    = (const int*)d_in[1];
    const int*   batch = (const int*)d_in[2];
    const float* W[4]    = {(const float*)d_in[3],  (const float*)d_in[7],
                            (const float*)d_in[11], (const float*)d_in[15]};
    const float* asrc[4] = {(const float*)d_in[4],  (const float*)d_in[8],
                            (const float*)d_in[12], (const float*)d_in[16]};
    const float* adst[4] = {(const float*)d_in[5],  (const float*)d_in[9],
                            (const float*)d_in[13], (const float*)d_in[17]};
    const float* bias[4] = {(const float*)d_in[6],  (const float*)d_in[10],
                            (const float*)d_in[14], (const float*)d_in[18]};
    const float* lin_w = (const float*)d_in[19];
    const float* lin_b = (const float*)d_in[20];
    float* out = (float*)d_out;

    const int* srcv = ei;
    const int* dstv = ei + EEDGE;

    void *ph, *px, *pas, *pad, *ppool, *pcnt, *pdeg, *pcur, *prp, *pcs;
    cudaGetSymbolAddress(&ph,   g_h);
    cudaGetSymbolAddress(&px,   g_x);
    cudaGetSymbolAddress(&pas,  g_as);
    cudaGetSymbolAddress(&pad,  g_ad);
    cudaGetSymbolAddress(&ppool,g_pool);
    cudaGetSymbolAddress(&pcnt, g_cnt);
    cudaGetSymbolAddress(&pdeg, g_deg);
    cudaGetSymbolAddress(&pcur, g_cursor);
    cudaGetSymbolAddress(&prp,  g_rowptr);
    cudaGetSymbolAddress(&pcs,  g_csrc);

    const int SMEM_TC = 4 * 128 * SX * (int)sizeof(__nv_bfloat16);
    cudaFuncSetAttribute(gemm_tc_k, cudaFuncAttributeMaxDynamicSharedMemorySize, SMEM_TC);

    // #1: layer-1 GEMM+alpha fused with dst-degree histogram
    fused1_k<<<GB1 + HB1, 256>>>(x, W[0], asrc[0], adst[0], dstv, (int*)pdeg,
                                 (float*)ph, (float*)pas, (float*)pad);
    // #2: scan (+ zero deg for next replay, zero pool accumulators)
    scan_k<<<1, 1024>>>((int*)pdeg, (int*)prp, (float*)ppool, (float*)pcnt);
    // #3: scatter into CSR
    scatter_k<<<(EEDGE + 255) / 256, 256>>>(srcv, dstv, (const int*)prp,
                                            (int*)pcur, (int*)pcs);
    // #4: layer-1 aggregation (profiled launch) — also re-zeros cursor
    agg_k<<<(NN * 32 + 255) / 256, 256>>>((const int*)prp, (const int*)pcs,
                                          (const float*)pas, (const float*)pad,
                                          (const float*)ph, bias[0], (float*)px,
                                          (int*)pcur);

    // layers 2-4
    for (int l = 1; l < 4; l++) {
        gemm_tc_k<<<(NN + 127) / 128, 256, SMEM_TC>>>((const float*)px, W[l],
                                                      asrc[l], adst[l],
                                                      (float*)ph, (float*)pas, (float*)pad);
        agg_k<<<(NN * 32 + 255) / 256, 256>>>((const int*)prp, (const int*)pcs,
                                              (const float*)pas, (const float*)pad,
                                              (const float*)ph, bias[l], (float*)px,
                                              (int*)nullptr);
    }

    // pooling + classifier
    pool_k<<<(NN + PB - 1) / PB, PB>>>(batch, (const float*)px,
                                       (float*)ppool, (float*)pcnt);
    final_k<<<1, 512>>>((const float*)ppool, (const float*)pcnt, lin_w, lin_b, out);
}

// round 16
// speedup vs baseline: 1.0725x; 1.0725x over previous
#include <cuda_runtime.h>
#include <cuda_bf16.h>

#define NN 50000
#define EEDGE 500000
#define GG 64
#define HH 2
#define FF 128          // H*D
#define CC 5
#define SLOPE 0.2f
#define SX 136          // padded bf16 row stride (bank = 4*grp+qd -> conflict-free)
#define GB1 6250        // warp-per-node blocks in fused1_k (50000/8)
#define HB1 1954        // hist blocks ((E+255)/256)
#define WB1 192         // W-presplit blocks (3 layers x 64)
#define SB  489         // scatter blocks in scan_scatter_k (ceil(E/1024))

// ---------------- scratch (device globals) ------------------------------------
// Replay invariants: g_deg, g_cursor, g_flag, g_done are zero on entry to each
// replay (zero at load; re-zeroed within the replay after last use).
__device__ float          g_h[NN * FF];     // pre-aggregation features (fp32)
__device__ __nv_bfloat16  g_xhi[NN * FF];   // layer output, bf16 hi
__device__ __nv_bfloat16  g_xlo[NN * FF];   // layer output, bf16 lo
__device__ __nv_bfloat16  g_whi[3 * FF * FF]; // presplit W (layers 2-4), [n][k]
__device__ __nv_bfloat16  g_wlo[3 * FF * FF];
__device__ float          g_as[NN * HH];
__device__ float          g_ad[NN * HH];
__device__ float          g_pool[GG * FF];
__device__ float          g_cnt[GG];
__device__ int            g_deg[NN];
__device__ int            g_cursor[NN];
__device__ int            g_rowptr[NN + 1];
__device__ int            g_csrc[EEDGE];
__device__ int            g_flag;
__device__ int            g_done;

// ---------------- launch #1: layer-1 GEMM+alpha | dst hist | W presplit --------
__global__ void fused1_k(const float* __restrict__ x, const float* __restrict__ W1,
                         const float* __restrict__ asrc, const float* __restrict__ adst,
                         const int* __restrict__ dstv, int* __restrict__ deg,
                         float* __restrict__ h, float* __restrict__ as_,
                         float* __restrict__ ad_,
                         const float* __restrict__ W2, const float* __restrict__ W3,
                         const float* __restrict__ W4,
                         __nv_bfloat16* __restrict__ whi, __nv_bfloat16* __restrict__ wlo) {
    int tid = threadIdx.x;
    if (blockIdx.x < GB1) {
        // ---- GEMM [N,4]x[4,128] + alpha, warp per node ----
        __shared__ float Ws[4 * FF];
        for (int i = tid; i < 4 * FF; i += 256) Ws[i] = W1[i];
        __syncthreads();
        int n = blockIdx.x * 8 + (tid >> 5);
        int lane = tid & 31;
        const float* xr = x + n * 4;
        float x0 = xr[0], x1 = xr[1], x2 = xr[2], x3 = xr[3];
        float v0 = x0 * Ws[lane]      + x1 * Ws[128 + lane]      + x2 * Ws[256 + lane]      + x3 * Ws[384 + lane];
        float v1 = x0 * Ws[lane + 32] + x1 * Ws[128 + lane + 32] + x2 * Ws[256 + lane + 32] + x3 * Ws[384 + lane + 32];
        float v2 = x0 * Ws[lane + 64] + x1 * Ws[128 + lane + 64] + x2 * Ws[256 + lane + 64] + x3 * Ws[384 + lane + 64];
        float v3 = x0 * Ws[lane + 96] + x1 * Ws[128 + lane + 96] + x2 * Ws[256 + lane + 96] + x3 * Ws[384 + lane + 96];
        float* hr = h + (size_t)n * FF;
        hr[lane] = v0; hr[lane + 32] = v1; hr[lane + 64] = v2; hr[lane + 96] = v3;
        float s0 = v0 * asrc[lane] + v1 * asrc[lane + 32];
        float d0 = v0 * adst[lane] + v1 * adst[lane + 32];
        float s1 = v2 * asrc[64 + lane] + v3 * asrc[96 + lane];
        float d1 = v2 * adst[64 + lane] + v3 * adst[96 + lane];
#pragma unroll
        for (int o = 16; o; o >>= 1) {
            s0 += __shfl_xor_sync(0xffffffffu, s0, o);
            d0 += __shfl_xor_sync(0xffffffffu, d0, o);
            s1 += __shfl_xor_sync(0xffffffffu, s1, o);
            d1 += __shfl_xor_sync(0xffffffffu, d1, o);
        }
        if (lane == 0) {
            as_[n * 2] = s0; as_[n * 2 + 1] = s1;
            ad_[n * 2] = d0; ad_[n * 2 + 1] = d1;
        }
    } else if (blockIdx.x < GB1 + HB1) {
        // ---- dst-degree histogram ----
        int e = (blockIdx.x - GB1) * 256 + tid;
        if (e < EEDGE) atomicAdd(&deg[dstv[e]], 1);
    } else {
        // ---- W presplit (transposed [n][k], hi/lo bf16), layers 2-4 ----
        int wb = blockIdx.x - GB1 - HB1;          // 0..191
        int l = wb >> 6;                          // 0..2
        int off = (wb & 63) * 256 + tid;          // 0..16383 = n*128+k
        int n = off >> 7, k = off & 127;
        const float* Wp = (l == 0) ? W2 : (l == 1) ? W3 : W4;
        float wv = Wp[k * FF + n];
        __nv_bfloat16 hi = __float2bfloat16_rn(wv);
        __nv_bfloat16 lo = __float2bfloat16_rn(wv - __bfloat162float(hi));
        whi[l * FF * FF + off] = hi;
        wlo[l * FF * FF + off] = lo;
    }
}

// ---------------- launch #2: scan + scatter (doorbell-fused) -------------------
__global__ void scan_scatter_k(int* __restrict__ deg, int* __restrict__ rowptr,
                               const int* __restrict__ srcv, const int* __restrict__ dstv,
                               int* __restrict__ cursor, int* __restrict__ csrc,
                               float* __restrict__ pooled, float* __restrict__ cnt,
                               int* __restrict__ flag, int* __restrict__ done) {
    int t = threadIdx.x;
    if (blockIdx.x == 0) {
        // ---- exclusive scan over deg + zero pool accumulators + re-zero deg ----
        __shared__ int part[1024];
        const int CH = (NN + 1023) / 1024;
        for (int i = t; i < GG * FF; i += 1024) pooled[i] = 0.f;
        if (t < GG) cnt[t] = 0.f;
        int base = t * CH;
        int s = 0;
        for (int i = 0; i < CH; i++) {
            int idx = base + i;
            if (idx < NN) s += deg[idx];
        }
        part[t] = s;
        __syncthreads();
        for (int off = 1; off < 1024; off <<= 1) {
            int v = (t >= off) ? part[t - off] : 0;
            __syncthreads();
            part[t] += v;
            __syncthreads();
        }
        int run = (t == 0) ? 0 : part[t - 1];
        for (int i = 0; i < CH; i++) {
            int idx = base + i;
            if (idx <= NN) {
                rowptr[idx] = run;
                if (idx < NN) { run += deg[idx]; deg[idx] = 0; }
            }
        }
        __threadfence();      // every thread publishes its rowptr writes
        __syncthreads();
        if (t == 0) atomicExch(flag, 1);   // doorbell
    } else {
        if (t == 0) { while (atomicAdd(flag, 0) == 0) {} __threadfence(); }
        __syncthreads();
        int e = (blockIdx.x - 1) * 1024 + t;
        if (e < EEDGE) {
            int d = dstv[e];
            int pos = rowptr[d] + atomicAdd(&cursor[d], 1);
            csrc[pos] = srcv[e];
        }
        __syncthreads();
        if (t == 0) {
            int v = atomicAdd(done, 1);
            if (v == SB - 1) { *done = 0; atomicExch(flag, 0); }  // reset for next replay
        }
    }
}

// ---------------- tensor-core GEMM (layers 2-4), alpha fused -------------------
__device__ __forceinline__ void mma_bf16(float* d, const unsigned* a, const unsigned* b) {
    asm volatile(
        "mma.sync.aligned.m16n8k16.row.col.f32.bf16.bf16.f32 "
        "{%0,%1,%2,%3}, {%4,%5,%6,%7}, {%8,%9}, {%0,%1,%2,%3};"
        : "+f"(d[0]), "+f"(d[1]), "+f"(d[2]), "+f"(d[3])
        : "r"(a[0]), "r"(a[1]), "r"(a[2]), "r"(a[3]), "r"(b[0]), "r"(b[1]));
}

__global__ void __launch_bounds__(256, 1)
gemm_tc_k(const __nv_bfloat16* __restrict__ Xhi_g, const __nv_bfloat16* __restrict__ Xlo_g,
          const __nv_bfloat16* __restrict__ Whi_g, const __nv_bfloat16* __restrict__ Wlo_g,
          const float* __restrict__ asrc, const float* __restrict__ adst,
          float* __restrict__ h, float* __restrict__ as_, float* __restrict__ ad_) {
    extern __shared__ __nv_bfloat16 sm[];
    __nv_bfloat16* Xhi = sm;
    __nv_bfloat16* Xlo = sm + 128 * SX;
    __nv_bfloat16* Whi = sm + 2 * 128 * SX;
    __nv_bfloat16* Wlo = sm + 3 * 128 * SX;

    int tid = threadIdx.x;
    int row0 = blockIdx.x * 128;

    // vectorized prologue: 8 bf16 per uint4, no conversion work
    const uint4* WhiV = reinterpret_cast<const uint4*>(Whi_g);
    const uint4* WloV = reinterpret_cast<const uint4*>(Wlo_g);
    const uint4* XhiV = reinterpret_cast<const uint4*>(Xhi_g);
    const uint4* XloV = reinterpret_cast<const uint4*>(Xlo_g);
    const uint4 z4 = make_uint4(0, 0, 0, 0);
    for (int i = tid; i < 128 * 16; i += 256) {
        int n = i >> 4, q = i & 15;
        *reinterpret_cast<uint4*>(&Whi[n * SX + q * 8]) = WhiV[i];
        *reinterpret_cast<uint4*>(&Wlo[n * SX + q * 8]) = WloV[i];
        int gr = row0 + n;
        bool ok = gr < NN;
        *reinterpret_cast<uint4*>(&Xhi[n * SX + q * 8]) = ok ? XhiV[gr * 16 + q] : z4;
        *reinterpret_cast<uint4*>(&Xlo[n * SX + q * 8]) = ok ? XloV[gr * 16 + q] : z4;
    }
    __syncthreads();

    int w = tid >> 5;
    int lane = tid & 31;
    int grp = lane >> 2, qd = lane & 3;
    int mr = (w & 3) * 32;
    int nc = (w >> 2) * 64;
    int head = nc >> 6;

    float acc[2][8][4];
#pragma unroll
    for (int mt = 0; mt < 2; mt++)
#pragma unroll
        for (int nt = 0; nt < 8; nt++)
#pragma unroll
            for (int q = 0; q < 4; q++) acc[mt][nt][q] = 0.f;

#pragma unroll 2
    for (int ks = 0; ks < 8; ks++) {
        int k0 = ks * 16;
        unsigned Ah[2][4], Al[2][4];
#pragma unroll
        for (int mt = 0; mt < 2; mt++) {
            int r = mr + mt * 16 + grp;
            int o = r * SX + k0 + qd * 2;
            Ah[mt][0] = *reinterpret_cast<const unsigned*>(&Xhi[o]);
            Ah[mt][1] = *reinterpret_cast<const unsigned*>(&Xhi[o + 8 * SX]);
            Ah[mt][2] = *reinterpret_cast<const unsigned*>(&Xhi[o + 8]);
            Ah[mt][3] = *reinterpret_cast<const unsigned*>(&Xhi[o + 8 * SX + 8]);
            Al[mt][0] = *reinterpret_cast<const unsigned*>(&Xlo[o]);
            Al[mt][1] = *reinterpret_cast<const unsigned*>(&Xlo[o + 8 * SX]);
            Al[mt][2] = *reinterpret_cast<const unsigned*>(&Xlo[o + 8]);
            Al[mt][3] = *reinterpret_cast<const unsigned*>(&Xlo[o + 8 * SX + 8]);
        }
        unsigned Bh[8][2], Bl[8][2];
#pragma unroll
        for (int nt = 0; nt < 8; nt++) {
            int cidx = nc + nt * 8 + grp;
            int o = cidx * SX + k0 + qd * 2;
            Bh[nt][0] = *reinterpret_cast<const unsigned*>(&Whi[o]);
            Bh[nt][1] = *reinterpret_cast<const unsigned*>(&Whi[o + 8]);
            Bl[nt][0] = *reinterpret_cast<const unsigned*>(&Wlo[o]);
            Bl[nt][1] = *reinterpret_cast<const unsigned*>(&Wlo[o + 8]);
        }
#pragma unroll
        for (int mt = 0; mt < 2; mt++)
#pragma unroll
            for (int nt = 0; nt < 8; nt++) {
                mma_bf16(acc[mt][nt], Ah[mt], Bh[nt]);
                mma_bf16(acc[mt][nt], Ah[mt], Bl[nt]);
                mma_bf16(acc[mt][nt], Al[mt], Bh[nt]);
            }
    }

    float av[8][2], dv[8][2];
#pragma unroll
    for (int nt = 0; nt < 8; nt++)
#pragma unroll
        for (int c = 0; c < 2; c++) {
            int col = head * 64 + nt * 8 + qd * 2 + c;
            av[nt][c] = asrc[col];
            dv[nt][c] = adst[col];
        }

#pragma unroll
    for (int mt = 0; mt < 2; mt++) {
        int r0 = row0 + mr + mt * 16 + grp;
        float sa = 0.f, sd = 0.f, sa2 = 0.f, sd2 = 0.f;
#pragma unroll
        for (int nt = 0; nt < 8; nt++) {
            int col = nc + nt * 8 + qd * 2;
            if (r0 < NN)
                *reinterpret_cast<float2*>(&h[(size_t)r0 * FF + col]) =
                    make_float2(acc[mt][nt][0], acc[mt][nt][1]);
            if (r0 + 8 < NN)
                *reinterpret_cast<float2*>(&h[(size_t)(r0 + 8) * FF + col]) =
                    make_float2(acc[mt][nt][2], acc[mt][nt][3]);
#pragma unroll
            for (int c = 0; c < 2; c++) {
                sa  += acc[mt][nt][c]     * av[nt][c];
                sd  += acc[mt][nt][c]     * dv[nt][c];
                sa2 += acc[mt][nt][2 + c] * av[nt][c];
                sd2 += acc[mt][nt][2 + c] * dv[nt][c];
            }
        }
#pragma unroll
        for (int o = 1; o <= 2; o <<= 1) {
            sa  += __shfl_xor_sync(0xffffffffu, sa,  o);
            sd  += __shfl_xor_sync(0xffffffffu, sd,  o);
            sa2 += __shfl_xor_sync(0xffffffffu, sa2, o);
            sd2 += __shfl_xor_sync(0xffffffffu, sd2, o);
        }
        if (qd == 0) {
            if (r0 < NN)     { as_[2 * r0 + head] = sa;        ad_[2 * r0 + head] = sd; }
            if (r0 + 8 < NN) { as_[2 * (r0 + 8) + head] = sa2; ad_[2 * (r0 + 8) + head] = sd2; }
        }
    }
}

// ---------------- fused aggregation --------------------------------------------
// Warp per node. Fast path (deg<=32): softmax in registers; (idx,w0,w1) packed
// into one int4 -> single LDS.128 per edge; 32-bit gather addressing; MLP=8.
// Output written as bf16 hi/lo pair (next GEMM's input; pool reconstructs).
__global__ void agg_k(const int* __restrict__ rowptr, const int* __restrict__ csrc,
                      const float* __restrict__ as_, const float* __restrict__ ad_,
                      const float* __restrict__ h, const float* __restrict__ b,
                      __nv_bfloat16* __restrict__ xhi, __nv_bfloat16* __restrict__ xlo,
                      int* __restrict__ cz) {
    __shared__ int4 spk[8][32];
    int n = (blockIdx.x * blockDim.x + threadIdx.x) >> 5;
    int w = (threadIdx.x >> 5);
    int lane = threadIdx.x & 31;
    if (n >= NN) return;
    if (cz && lane == 0) cz[n] = 0;   // restore cursor invariant (layer 0 only)
    int beg = rowptr[n], end = rowptr[n + 1];
    int deg = end - beg;
    float ad0 = ad_[2 * n], ad1 = ad_[2 * n + 1];

    float4 acc = make_float4(0.f, 0.f, 0.f, 0.f);
    const float4* hb = reinterpret_cast<const float4*>(h) + lane;

    if (deg <= 32) {
        int sreg = 0;
        float e0 = -1e30f, e1 = -1e30f;
        if (lane < deg) {
            sreg = csrc[beg + lane];
            float2 sv = reinterpret_cast<const float2*>(as_)[sreg];
            e0 = sv.x + ad0; e0 = e0 > 0.f ? e0 : SLOPE * e0;
            e1 = sv.y + ad1; e1 = e1 > 0.f ? e1 : SLOPE * e1;
        }
        float m0 = e0, m1 = e1;
#pragma unroll
        for (int o = 16; o; o >>= 1) {
            m0 = fmaxf(m0, __shfl_xor_sync(0xffffffffu, m0, o));
            m1 = fmaxf(m1, __shfl_xor_sync(0xffffffffu, m1, o));
        }
        float p0 = (lane < deg) ? __expf(e0 - m0) : 0.f;
        float p1 = (lane < deg) ? __expf(e1 - m1) : 0.f;
        float s0 = p0, s1 = p1;
#pragma unroll
        for (int o = 16; o; o >>= 1) {
            s0 += __shfl_xor_sync(0xffffffffu, s0, o);
            s1 += __shfl_xor_sync(0xffffffffu, s1, o);
        }
        spk[w][lane] = make_int4(sreg * 32,
                                 __float_as_int(p0 / (s0 + 1e-16f)),
                                 __float_as_int(p1 / (s1 + 1e-16f)), 0);
        __syncwarp();

        const int4* sp = spk[w];
        bool h0 = lane < 16;
        int j = 0;
        for (; j + 8 <= deg; j += 8) {
            float4 v[8]; float wg[8];
#pragma unroll
            for (int u = 0; u < 8; u++) {
                int4 e = sp[j + u];
                wg[u] = h0 ? __int_as_float(e.y) : __int_as_float(e.z);
                v[u] = hb[e.x];
            }
#pragma unroll
            for (int u = 0; u < 8; u++) {
                acc.x += v[u].x * wg[u]; acc.y += v[u].y * wg[u];
                acc.z += v[u].z * wg[u]; acc.w += v[u].w * wg[u];
            }
        }
#pragma unroll
        for (int u = 0; u < 7; u++) {
            int jj = j + u;
            if (jj < deg) {
                int4 e = sp[jj];
                float wg = h0 ? __int_as_float(e.y) : __int_as_float(e.z);
                float4 v = hb[e.x];
                acc.x += v.x * wg; acc.y += v.y * wg;
                acc.z += v.z * wg; acc.w += v.w * wg;
            }
        }
    } else {
        // fallback (rare): online softmax + sequential gather
        float m0 = -1e30f, s0 = 0.f, m1 = -1e30f, s1 = 0.f;
        for (int i = beg + lane; i < end; i += 32) {
            int s = csrc[i];
            float e0 = as_[2 * s] + ad0;     e0 = e0 > 0.f ? e0 : SLOPE * e0;
            float e1 = as_[2 * s + 1] + ad1; e1 = e1 > 0.f ? e1 : SLOPE * e1;
            float nm0 = fmaxf(m0, e0);
            s0 = s0 * __expf(m0 - nm0) + __expf(e0 - nm0); m0 = nm0;
            float nm1 = fmaxf(m1, e1);
            s1 = s1 * __expf(m1 - nm1) + __expf(e1 - nm1); m1 = nm1;
        }
#pragma unroll
        for (int o = 16; o; o >>= 1) {
            float om = __shfl_xor_sync(0xffffffffu, m0, o);
            float os = __shfl_xor_sync(0xffffffffu, s0, o);
            float nm = fmaxf(m0, om);
            s0 = s0 * __expf(m0 - nm) + os * __expf(om - nm); m0 = nm;
            om = __shfl_xor_sync(0xffffffffu, m1, o);
            os = __shfl_xor_sync(0xffffffffu, s1, o);
            nm = fmaxf(m1, om);
            s1 = s1 * __expf(m1 - nm) + os * __expf(om - nm); m1 = nm;
        }
        float inv0 = 1.f / (s0 + 1e-16f);
        float inv1 = 1.f / (s1 + 1e-16f);
        for (int i = beg; i < end; i++) {
            int s = csrc[i];
            float e0 = as_[2 * s] + ad0;     e0 = e0 > 0.f ? e0 : SLOPE * e0;
            float e1 = as_[2 * s + 1] + ad1; e1 = e1 > 0.f ? e1 : SLOPE * e1;
            float p = (lane < 16) ? __expf(e0 - m0) * inv0 : __expf(e1 - m1) * inv1;
            float4 v = hb[s * 32];
            acc.x += v.x * p; acc.y += v.y * p; acc.z += v.z * p; acc.w += v.w * p;
        }
    }

    float4 bv = reinterpret_cast<const float4*>(b)[lane];
    float r0 = fmaxf(acc.x + bv.x, 0.f);
    float r1 = fmaxf(acc.y + bv.y, 0.f);
    float r2 = fmaxf(acc.z + bv.z, 0.f);
    float r3 = fmaxf(acc.w + bv.w, 0.f);

    // split to bf16 hi/lo and store (4 hi = 8B, 4 lo = 8B per lane)
    __nv_bfloat16 h0b = __float2bfloat16_rn(r0);
    __nv_bfloat16 h1b = __float2bfloat16_rn(r1);
    __nv_bfloat16 h2b = __float2bfloat16_rn(r2);
    __nv_bfloat16 h3b = __float2bfloat16_rn(r3);
    __nv_bfloat16 l0b = __float2bfloat16_rn(r0 - __bfloat162float(h0b));
    __nv_bfloat16 l1b = __float2bfloat16_rn(r1 - __bfloat162float(h1b));
    __nv_bfloat16 l2b = __float2bfloat16_rn(r2 - __bfloat162float(h2b));
    __nv_bfloat16 l3b = __float2bfloat16_rn(r3 - __bfloat162float(h3b));
    __nv_bfloat162 hp0; hp0.x = h0b; hp0.y = h1b;
    __nv_bfloat162 hp1; hp1.x = h2b; hp1.y = h3b;
    __nv_bfloat162 lp0; lp0.x = l0b; lp0.y = l1b;
    __nv_bfloat162 lp1; lp1.x = l2b; lp1.y = l3b;
    reinterpret_cast<__nv_bfloat162*>(xhi + (size_t)n * FF)[lane * 2]     = hp0;
    reinterpret_cast<__nv_bfloat162*>(xhi + (size_t)n * FF)[lane * 2 + 1] = hp1;
    reinterpret_cast<__nv_bfloat162*>(xlo + (size_t)n * FF)[lane * 2]     = lp0;
    reinterpret_cast<__nv_bfloat162*>(xlo + (size_t)n * FF)[lane * 2 + 1] = lp1;
}

// ---------------- pooling + classifier -----------------------------------------
#define PB 128
__global__ void pool_k(const int* __restrict__ batch,
                       const __nv_bfloat16* __restrict__ xhi,
                       const __nv_bfloat16* __restrict__ xlo,
                       float* __restrict__ pooled, float* __restrict__ cnt) {
    int c = threadIdx.x;
    int n0 = blockIdx.x * PB;
    int nend = min(n0 + PB, NN);
    if (n0 >= NN) return;
    int curg = batch[n0];
    float run = 0.f;
    for (int n = n0; n < nend; n++) {
        int g = batch[n];
        if (g != curg) {
            atomicAdd(&pooled[curg * FF + c], run);
            run = 0.f; curg = g;
        }
        run += __bfloat162float(xhi[(size_t)n * FF + c]) +
               __bfloat162float(xlo[(size_t)n * FF + c]);
    }
    atomicAdd(&pooled[curg * FF + c], run);
    if (c == 0) {
        int cg = batch[n0]; float cr = 0.f;
        for (int n = n0; n < nend; n++) {
            int g = batch[n];
            if (g != cg) { atomicAdd(&cnt[cg], cr); cr = 0.f; cg = g; }
            cr += 1.f;
        }
        atomicAdd(&cnt[cg], cr);
    }
}

__global__ void final_k(const float* __restrict__ pooled, const float* __restrict__ cnt,
                        const float* __restrict__ lw, const float* __restrict__ lb,
                        float* __restrict__ out) {
    int t = threadIdx.x;
    if (t >= GG * CC) return;
    int g = t / CC, c = t % CC;
    float inv = 1.f / fmaxf(cnt[g], 1.f);
    float acc = lb[c];
    for (int k = 0; k < FF; k++)
        acc += pooled[g * FF + k] * inv * lw[k * CC + c];
    out[t] = 1.f / (1.f + expf(-acc));
}

// ---------------- launch --------------------------------------------------------
extern "C" void kernel_launch(void* const* d_in, const int* in_sizes, int n_in,
                              void* d_out, int out_size) {
    const float* x     = (const float*)d_in[0];
    const int*   ei    = (const int*)d_in[1];
    const int*   batch = (const int*)d_in[2];
    const float* W[4]    = {(const float*)d_in[3],  (const float*)d_in[7],
                            (const float*)d_in[11], (const float*)d_in[15]};
    const float* asrc[4] = {(const float*)d_in[4],  (const float*)d_in[8],
                            (const float*)d_in[12], (const float*)d_in[16]};
    const float* adst[4] = {(const float*)d_in[5],  (const float*)d_in[9],
                            (const float*)d_in[13], (const float*)d_in[17]};
    const float* bias[4] = {(const float*)d_in[6],  (const float*)d_in[10],
                            (const float*)d_in[14], (const float*)d_in[18]};
    const float* lin_w = (const float*)d_in[19];
    const float* lin_b = (const float*)d_in[20];
    float* out = (float*)d_out;

    const int* srcv = ei;
    const int* dstv = ei + EEDGE;

    void *ph, *pxhi, *pxlo, *pwhi, *pwlo, *pas, *pad, *ppool, *pcnt;
    void *pdeg, *pcur, *prp, *pcs, *pflag, *pdone;
    cudaGetSymbolAddress(&ph,    g_h);
    cudaGetSymbolAddress(&pxhi,  g_xhi);
    cudaGetSymbolAddress(&pxlo,  g_xlo);
    cudaGetSymbolAddress(&pwhi,  g_whi);
    cudaGetSymbolAddress(&pwlo,  g_wlo);
    cudaGetSymbolAddress(&pas,   g_as);
    cudaGetSymbolAddress(&pad,   g_ad);
    cudaGetSymbolAddress(&ppool, g_pool);
    cudaGetSymbolAddress(&pcnt,  g_cnt);
    cudaGetSymbolAddress(&pdeg,  g_deg);
    cudaGetSymbolAddress(&pcur,  g_cursor);
    cudaGetSymbolAddress(&prp,   g_rowptr);
    cudaGetSymbolAddress(&pcs,   g_csrc);
    cudaGetSymbolAddress(&pflag, g_flag);
    cudaGetSymbolAddress(&pdone, g_done);

    const int SMEM_TC = 4 * 128 * SX * (int)sizeof(__nv_bfloat16);   // 139264 B
    cudaFuncSetAttribute(gemm_tc_k, cudaFuncAttributeMaxDynamicSharedMemorySize, SMEM_TC);

    // #1: layer-1 GEMM+alpha | dst histogram | W presplit (layers 2-4)
    fused1_k<<<GB1 + HB1 + WB1, 256>>>(x, W[0], asrc[0], adst[0], dstv, (int*)pdeg,
                                       (float*)ph, (float*)pas, (float*)pad,
                                       W[1], W[2], W[3],
                                       (__nv_bfloat16*)pwhi, (__nv_bfloat16*)pwlo);
    // #2: scan + scatter (doorbell); zeroes pool/cnt, re-zeroes deg, resets flag/done
    scan_scatter_k<<<1 + SB, 1024>>>((int*)pdeg, (int*)prp, srcv, dstv,
                                     (int*)pcur, (int*)pcs,
                                     (float*)ppool, (float*)pcnt,
                                     (int*)pflag, (int*)pdone);
    // #3: layer-1 aggregation (re-zeros cursor)
    agg_k<<<(NN * 32 + 255) / 256, 256>>>((const int*)prp, (const int*)pcs,
                                          (const float*)pas, (const float*)pad,
                                          (const float*)ph, bias[0],
                                          (__nv_bfloat16*)pxhi, (__nv_bfloat16*)pxlo,
                                          (int*)pcur);

    // layers 2-4: #4 is gemm_tc_k (profiled next round)
    for (int l = 1; l < 4; l++) {
        gemm_tc_k<<<(NN + 127) / 128, 256, SMEM_TC>>>(
            (const __nv_bfloat16*)pxhi, (const __nv_bfloat16*)pxlo,
            (const __nv_bfloat16*)pwhi + (size_t)(l - 1) * FF * FF,
            (const __nv_bfloat16*)pwlo + (size_t)(l - 1) * FF * FF,
            asrc[l], adst[l],
            (float*)ph, (float*)pas, (float*)pad);
        agg_k<<<(NN * 32 + 255) / 256, 256>>>((const int*)prp, (const int*)pcs,
                                              (const float*)pas, (const float*)pad,
                                              (const float*)ph, bias[l],
                                              (__nv_bfloat16*)pxhi, (__nv_bfloat16*)pxlo,
                                              (int*)nullptr);
    }

    // pooling + classifier
    pool_k<<<(NN + PB - 1) / PB, PB>>>(batch, (const __nv_bfloat16*)pxhi,
                                       (const __nv_bfloat16*)pxlo,
                                       (float*)ppool, (float*)pcnt);
    final_k<<<1, 512>>>((const float*)ppool, (const float*)pcnt, lin_w, lin_b, out);
}